// round 1
// baseline (speedup 1.0000x reference)
#include <cuda_runtime.h>
#include <math.h>

#define BB   16
#define CIN  128
#define COUT 256
#define KK   9
#define HH   56
#define WW   56
#define HW   3136
#define KDIM (CIN*KK)   // 1152

// ---------------- device scratch (no allocations allowed) ----------------
__device__ float g_ctx[BB*CIN];
__device__ float g_attn_sp[BB*KK];
__device__ float g_attn_in[BB*CIN];
__device__ float g_attn_out[BB*COUT];
__device__ float g_dyn[(size_t)BB*COUT*KDIM];   // 16*294912 floats = 18.9 MB

// ---------------- 1) context = mean over H,W ----------------
__global__ void k_context(const float* __restrict__ x) {
    int row = blockIdx.x;                    // b*CIN + c  (2048 rows)
    const float* p = x + (size_t)row * HW;
    float s = 0.f;
    for (int i = threadIdx.x; i < HW; i += 256) s += p[i];
    __shared__ float sm[256];
    sm[threadIdx.x] = s; __syncthreads();
    #pragma unroll
    for (int off = 128; off > 0; off >>= 1) {
        if (threadIdx.x < off) sm[threadIdx.x] += sm[threadIdx.x + off];
        __syncthreads();
    }
    if (threadIdx.x == 0) g_ctx[row] = sm[0] * (1.0f / HW);
}

// ---------------- 2) small attention heads (one warp per output) ----------
__global__ void k_attn(const float* __restrict__ fsw, const float* __restrict__ fsb,
                       const float* __restrict__ fiw, const float* __restrict__ fib,
                       const float* __restrict__ fow, const float* __restrict__ fob) {
    int gw   = (blockIdx.x * blockDim.x + threadIdx.x) >> 5;
    int lane = threadIdx.x & 31;
    const int NS = BB*KK, NI = BB*CIN, NO = BB*COUT;
    if (gw >= NS + NI + NO) return;
    int b; const float* wrow; float bias; float* dst;
    if (gw < NS) {
        b = gw / KK; int r = gw % KK;
        wrow = fsw + r*CIN; bias = fsb[r]; dst = &g_attn_sp[gw];
    } else if (gw < NS + NI) {
        int g = gw - NS; b = g / CIN; int r = g % CIN;
        wrow = fiw + r*CIN; bias = fib[r]; dst = &g_attn_in[g];
    } else {
        int g = gw - NS - NI; b = g / COUT; int r = g % COUT;
        wrow = fow + r*CIN; bias = fob[r]; dst = &g_attn_out[g];
    }
    const float* ctx = g_ctx + b*CIN;
    float s = 0.f;
    #pragma unroll
    for (int j = lane; j < CIN; j += 32) s += ctx[j] * wrow[j];
    #pragma unroll
    for (int o = 16; o > 0; o >>= 1) s += __shfl_down_sync(0xffffffffu, s, o);
    if (lane == 0) *dst = 1.f / (1.f + expf(-(s + bias)));
}

// ---------------- 3) fused big-GEMM + sigmoid + 5-way multiply ------------
// One thread per (o,i,kk) row: loads 128-f weight row once (512B), computes
// 16 dot products against the 16 contexts (8KB in smem), writes 16 dyn values.
__global__ __launch_bounds__(256) void k_dyn(const float* __restrict__ base_kernel,
                                             const float* __restrict__ fkw,
                                             const float* __restrict__ fkb) {
    __shared__ __align__(16) float ctx_s[BB*CIN];
    for (int i = threadIdx.x; i < BB*CIN; i += 256) ctx_s[i] = g_ctx[i];
    __syncthreads();

    int r = blockIdx.x * 256 + threadIdx.x;          // 0..294911
    const float4* wr = (const float4*)(fkw + (size_t)r * CIN);

    float acc[BB];
    #pragma unroll
    for (int b = 0; b < BB; b++) acc[b] = 0.f;

    #pragma unroll 4
    for (int j = 0; j < CIN/4; j++) {
        float4 w4 = wr[j];
        #pragma unroll
        for (int b = 0; b < BB; b++) {
            float4 c4 = *(const float4*)(ctx_s + b*CIN + j*4);
            acc[b] += w4.x*c4.x + w4.y*c4.y + w4.z*c4.z + w4.w*c4.w;
        }
    }

    int o   = r / KDIM;
    int rem = r - o*KDIM;
    int i   = rem / KK;
    int kk  = rem - i*KK;
    float bk = base_kernel[r];
    float fb = fkb[r];
    #pragma unroll
    for (int b = 0; b < BB; b++) {
        float sg = 1.f / (1.f + expf(-(acc[b] + fb)));
        float v  = bk * g_attn_out[b*COUT + o] * g_attn_in[b*CIN + i]
                      * g_attn_sp[b*KK + kk] * sg;
        g_dyn[(size_t)b * COUT * KDIM + r] = v;
    }
}

// ---------------- 4) per-sample conv as implicit GEMM ---------------------
// M=COUT=256, N=HW=3136, K=1152.  BM=128, BN=64, BK=16, thread tile 8x4.
#define BM 128
#define BN 64
#define BK 16

__global__ __launch_bounds__(256) void k_conv(const float* __restrict__ x,
                                              const float* __restrict__ bias,
                                              float* __restrict__ out) {
    int b  = blockIdx.z;
    int m0 = blockIdx.y * BM;
    int n0 = blockIdx.x * BN;
    const float* A = g_dyn + (size_t)b * COUT * KDIM;
    const float* X = x     + (size_t)b * CIN  * HW;

    __shared__ __align__(16) float As[BK][BM];
    __shared__ __align__(16) float Bs[BK][BN];

    int tid = threadIdx.x;
    int ty  = tid >> 4;          // 0..15 -> 8 output rows each
    int tx  = tid & 15;          // 0..15 -> 4 output cols each

    float acc[8][4];
    #pragma unroll
    for (int i = 0; i < 8; i++)
        #pragma unroll
        for (int j = 0; j < 4; j++) acc[i][j] = 0.f;

    // A-load mapping: 128x16 tile, 8 elems (2x float4) per thread
    int am = tid >> 1;           // 0..127
    int ak = (tid & 1) * 8;      // 0 or 8
    // B-load mapping: 16x64 tile, 4 elems per thread (im2col gather)
    int bk = tid >> 4;           // 0..15
    int bn = (tid & 15) * 4;

    for (int k0 = 0; k0 < KDIM; k0 += BK) {
        const float* ap = A + (size_t)(m0 + am) * KDIM + k0 + ak;
        float4 a0 = *(const float4*)ap;
        float4 a1 = *(const float4*)(ap + 4);
        As[ak+0][am] = a0.x; As[ak+1][am] = a0.y;
        As[ak+2][am] = a0.z; As[ak+3][am] = a0.w;
        As[ak+4][am] = a1.x; As[ak+5][am] = a1.y;
        As[ak+6][am] = a1.z; As[ak+7][am] = a1.w;

        int k  = k0 + bk;
        int ci = k / 9;
        int r9 = k - ci*9;
        int kh = r9 / 3 - 1;     // -1..1
        int kw = r9 - (r9/3)*3 - 1;
        const float* xc = X + (size_t)ci * HW;
        #pragma unroll
        for (int j = 0; j < 4; j++) {
            int n = n0 + bn + j;
            int h = n / WW + kh;
            int w = n - (n/WW)*WW + kw;
            float v = 0.f;
            if ((unsigned)h < HH && (unsigned)w < WW) v = xc[h*WW + w];
            Bs[bk][bn + j] = v;
        }
        __syncthreads();

        #pragma unroll
        for (int k2 = 0; k2 < BK; k2++) {
            float4 fa0 = *(const float4*)&As[k2][ty*8];
            float4 fa1 = *(const float4*)&As[k2][ty*8 + 4];
            float4 fb4 = *(const float4*)&Bs[k2][tx*4];
            float aa[8] = {fa0.x, fa0.y, fa0.z, fa0.w, fa1.x, fa1.y, fa1.z, fa1.w};
            float bv[4] = {fb4.x, fb4.y, fb4.z, fb4.w};
            #pragma unroll
            for (int i = 0; i < 8; i++)
                #pragma unroll
                for (int j = 0; j < 4; j++)
                    acc[i][j] += aa[i] * bv[j];
        }
        __syncthreads();
    }

    #pragma unroll
    for (int i = 0; i < 8; i++) {
        int o = m0 + ty*8 + i;
        float bi = bias[o];
        float* op = out + ((size_t)b * COUT + o) * HW + n0 + tx*4;
        float4 r4 = make_float4(acc[i][0] + bi, acc[i][1] + bi,
                                acc[i][2] + bi, acc[i][3] + bi);
        *(float4*)op = r4;
    }
}

// ---------------- launch ----------------
extern "C" void kernel_launch(void* const* d_in, const int* in_sizes, int n_in,
                              void* d_out, int out_size) {
    const float* x    = (const float*)d_in[0];
    const float* bk   = (const float*)d_in[1];
    const float* bias = (const float*)d_in[2];
    const float* fsw  = (const float*)d_in[3];
    const float* fsb  = (const float*)d_in[4];
    const float* fiw  = (const float*)d_in[5];
    const float* fib  = (const float*)d_in[6];
    const float* fow  = (const float*)d_in[7];
    const float* fob  = (const float*)d_in[8];
    const float* fkw  = (const float*)d_in[9];
    const float* fkb  = (const float*)d_in[10];
    float* out = (float*)d_out;

    k_context<<<BB*CIN, 256>>>(x);

    int total_warps = BB * (KK + CIN + COUT);              // 6288
    k_attn<<<(total_warps*32 + 255)/256, 256>>>(fsw, fsb, fiw, fib, fow, fob);

    k_dyn<<<(COUT*KDIM)/256, 256>>>(bk, fkw, fkb);

    dim3 grid(HW/BN, COUT/BM, BB);                         // (49, 2, 16)
    k_conv<<<grid, 256>>>(x, bias, out);
}

// round 3
// speedup vs baseline: 2.1154x; 2.1154x over previous
#include <cuda_runtime.h>
#include <cuda_bf16.h>
#include <cstdint>
#include <math.h>

#define BB   16
#define CIN  128
#define COUT 256
#define KK   9
#define HH   56
#define WW   56
#define HW   3136
#define KDIM (CIN*KK)   // 1152

// GEMM tiling (mma.sync bf16 path)
#define BM 128
#define BN 112          // 3136 = 28 * 112 ; covers exactly 2 image rows
#define BK 64           // bf16 K per mainloop chunk
#define NCHUNK (KDIM/BK) // 18

// ---------------- device scratch (no allocations allowed) ----------------
__device__ float g_ctx[BB*CIN];
__device__ float g_attn_sp[BB*KK];
__device__ float g_attn_in[BB*CIN];
__device__ float g_attn_out[BB*COUT];
__device__ __align__(16) __nv_bfloat16 g_dynA_hi[(size_t)BB*COUT*KDIM]; // 9.4MB
__device__ __align__(16) __nv_bfloat16 g_dynA_lo[(size_t)BB*COUT*KDIM]; // 9.4MB

// ======================= helpers =====================
__device__ __forceinline__ uint32_t smem_u32(const void* p) {
    uint32_t a;
    asm("{ .reg .u64 t; cvta.to.shared.u64 t, %1; cvt.u32.u64 %0, t; }"
        : "=r"(a) : "l"(p));
    return a;
}
__device__ __forceinline__ void ldm_x4(uint32_t* r, uint32_t addr) {
    asm volatile("ldmatrix.sync.aligned.m8n8.x4.shared.b16 {%0,%1,%2,%3}, [%4];"
        : "=r"(r[0]), "=r"(r[1]), "=r"(r[2]), "=r"(r[3]) : "r"(addr));
}
__device__ __forceinline__ void ldm_x2(uint32_t* r, uint32_t addr) {
    asm volatile("ldmatrix.sync.aligned.m8n8.x2.shared.b16 {%0,%1}, [%2];"
        : "=r"(r[0]), "=r"(r[1]) : "r"(addr));
}
__device__ __forceinline__ void mma16816(float* d, const uint32_t* a, const uint32_t* b) {
    asm volatile("mma.sync.aligned.m16n8k16.row.col.f32.bf16.bf16.f32 "
        "{%0,%1,%2,%3}, {%4,%5,%6,%7}, {%8,%9}, {%0,%1,%2,%3};"
        : "+f"(d[0]), "+f"(d[1]), "+f"(d[2]), "+f"(d[3])
        : "r"(a[0]), "r"(a[1]), "r"(a[2]), "r"(a[3]), "r"(b[0]), "r"(b[1]));
}
// 128B-row smem tile, XOR swizzle on 16B columns (conflict-free ldmatrix)
#define SWADDR(row, c16) ((uint32_t)((row) * 128 + (((c16) ^ ((row) & 7)) << 4)))

// ---------------- 1) context = mean over H,W ----------------
__global__ void k_context(const float* __restrict__ x) {
    int row = blockIdx.x;
    const float* p = x + (size_t)row * HW;
    float s = 0.f;
    for (int i = threadIdx.x; i < HW; i += 256) s += p[i];
    __shared__ float sm[256];
    sm[threadIdx.x] = s; __syncthreads();
    #pragma unroll
    for (int off = 128; off > 0; off >>= 1) {
        if (threadIdx.x < off) sm[threadIdx.x] += sm[threadIdx.x + off];
        __syncthreads();
    }
    if (threadIdx.x == 0) g_ctx[row] = sm[0] * (1.0f / HW);
}

// ---------------- 2) small attention heads ----------------
__global__ void k_attn(const float* __restrict__ fsw, const float* __restrict__ fsb,
                       const float* __restrict__ fiw, const float* __restrict__ fib,
                       const float* __restrict__ fow, const float* __restrict__ fob) {
    int gw   = (blockIdx.x * blockDim.x + threadIdx.x) >> 5;
    int lane = threadIdx.x & 31;
    const int NS = BB*KK, NI = BB*CIN, NO = BB*COUT;
    if (gw >= NS + NI + NO) return;
    int b; const float* wrow; float bias; float* dst;
    if (gw < NS) {
        b = gw / KK; int r = gw % KK;
        wrow = fsw + r*CIN; bias = fsb[r]; dst = &g_attn_sp[gw];
    } else if (gw < NS + NI) {
        int g = gw - NS; b = g / CIN; int r = g % CIN;
        wrow = fiw + r*CIN; bias = fib[r]; dst = &g_attn_in[g];
    } else {
        int g = gw - NS - NI; b = g / COUT; int r = g % COUT;
        wrow = fow + r*CIN; bias = fob[r]; dst = &g_attn_out[g];
    }
    const float* ctx = g_ctx + b*CIN;
    float s = 0.f;
    #pragma unroll
    for (int j = lane; j < CIN; j += 32) s += ctx[j] * wrow[j];
    #pragma unroll
    for (int o = 16; o > 0; o >>= 1) s += __shfl_down_sync(0xffffffffu, s, o);
    if (lane == 0) *dst = 1.f / (1.f + expf(-(s + bias)));
}

// ------- 3) fused big-GEMM + sigmoid + 5-way multiply -> bf16 hi/lo -------
__global__ __launch_bounds__(256) void k_dyn(const float* __restrict__ base_kernel,
                                             const float* __restrict__ fkw,
                                             const float* __restrict__ fkb) {
    __shared__ __align__(16) float ctx_s[BB*CIN];
    for (int i = threadIdx.x; i < BB*CIN; i += 256) ctx_s[i] = g_ctx[i];
    __syncthreads();

    int r = blockIdx.x * 256 + threadIdx.x;          // 0..294911
    const float4* wr = (const float4*)(fkw + (size_t)r * CIN);

    float acc[BB];
    #pragma unroll
    for (int b = 0; b < BB; b++) acc[b] = 0.f;

    #pragma unroll 4
    for (int j = 0; j < CIN/4; j++) {
        float4 w4 = wr[j];
        #pragma unroll
        for (int b = 0; b < BB; b++) {
            float4 c4 = *(const float4*)(ctx_s + b*CIN + j*4);
            acc[b] += w4.x*c4.x + w4.y*c4.y + w4.z*c4.z + w4.w*c4.w;
        }
    }

    int o   = r / KDIM;
    int rem = r - o*KDIM;
    int i   = rem / KK;
    int kk  = rem - i*KK;
    float bk = base_kernel[r];
    float fb = fkb[r];
    #pragma unroll
    for (int b = 0; b < BB; b++) {
        float sg = 1.f / (1.f + expf(-(acc[b] + fb)));
        float v  = bk * g_attn_out[b*COUT + o] * g_attn_in[b*CIN + i]
                      * g_attn_sp[b*KK + kk] * sg;
        __nv_bfloat16 hi = __float2bfloat16(v);
        __nv_bfloat16 lo = __float2bfloat16(v - __bfloat162float(hi));
        size_t idx = (size_t)b * COUT * KDIM + r;
        g_dynA_hi[idx] = hi;
        g_dynA_lo[idx] = lo;
    }
}

// -------- 4) tensor-core conv via mma.sync bf16 (3-term split) ------------
// SMEM: Ahi 16KB | Alo 16KB | Bhi 14KB | Blo 14KB  = 60KB dynamic
#define OFF_AHI  0
#define OFF_ALO  16384
#define OFF_BHI  32768
#define OFF_BLO  47104
#define SMEM_BYTES 61440

__global__ __launch_bounds__(256, 2) void k_conv_mma(const float* __restrict__ x,
                                                     const float* __restrict__ bias,
                                                     float* __restrict__ out) {
    extern __shared__ char smem[];
    uint32_t sbase = smem_u32(smem);
    int tid  = threadIdx.x;
    int wid  = tid >> 5;
    int lane = tid & 31;

    int b  = blockIdx.z;
    int m0 = blockIdx.y * BM;
    int n0 = blockIdx.x * BN;

    const __nv_bfloat16* Ahi = g_dynA_hi + (size_t)(b*COUT + m0) * KDIM;
    const __nv_bfloat16* Alo = g_dynA_lo + (size_t)(b*COUT + m0) * KDIM;
    const float* X = x + (size_t)b * CIN * HW;

    // warp tile: 32(m) x 56(n)
    int warp_m = (wid & 3) * 32;
    int warp_n = (wid >> 2) * 56;

    // --- per-lane ldmatrix row precompute ---
    // A x4: mat = lane>>3 (0..3): rows m (+8 if mat odd), k16-half = mat>>1
    int amat = lane >> 3;
    int arow0 = warp_m + (amat & 1) * 8 + (lane & 7);   // + t*16 added per tile
    int ac16  = amat >> 1;                               // 0 or 1 (k 0-7 / 8-15)
    // B x2: lanes: row = n + (lane&7), k16-half = (lane>>3)&1
    int brow_l = (lane & 7);
    int bc16   = (lane >> 3) & 1;

    // --- B gather mapping: kc = tid>>2 (0..63), q = tid&3 (28-row groups) ---
    int kc = tid >> 2;
    int q  = tid & 3;
    int h_local = q >> 1;
    int w0 = (q & 1) * 28;
    int nbase = q * 28;
    int hbase = blockIdx.x * 2;

    float acc[2][7][4];
    #pragma unroll
    for (int t = 0; t < 2; t++)
        #pragma unroll
        for (int nt = 0; nt < 7; nt++)
            #pragma unroll
            for (int i = 0; i < 4; i++) acc[t][nt][i] = 0.f;

    for (int kt = 0; kt < NCHUNK; kt++) {
        int k0 = kt * BK;

        // ---- load A hi/lo tiles: 128 rows x 64 bf16 (8 x 16B per row) ----
        #pragma unroll
        for (int c = 0; c < 4; c++) {
            int idx = c * 256 + tid;       // 0..1023
            int row = idx >> 3;
            int c16 = idx & 7;
            size_t src = (size_t)row * KDIM + k0 + c16 * 8;
            uint4 vh = *(const uint4*)(Ahi + src);
            uint4 vl = *(const uint4*)(Alo + src);
            uint32_t off = SWADDR(row, c16);
            *(uint4*)(smem + OFF_AHI + off) = vh;
            *(uint4*)(smem + OFF_ALO + off) = vl;
        }

        // ---- gather B tile (im2col) -> bf16 hi/lo, swizzled [n][k] ----
        {
            int k  = k0 + kc;
            int ci = k / 9;
            int r9 = k - ci * 9;
            int kh = r9 / 3;
            int kw = r9 - kh * 3;
            int h  = hbase + h_local + kh - 1;
            bool hok = (unsigned)h < HH;
            const float* xr = X + (size_t)ci * HW + h * WW;
            int c16b = kc >> 3;
            int b2   = (kc & 7) * 2;
            #pragma unroll 4
            for (int j = 0; j < 28; j++) {
                int w = w0 + j + kw - 1;
                float v = 0.f;
                if (hok && (unsigned)w < WW) v = xr[w];
                __nv_bfloat16 hi = __float2bfloat16(v);
                __nv_bfloat16 lo = __float2bfloat16(v - __bfloat162float(hi));
                int n = nbase + j;
                uint32_t off = SWADDR(n, c16b) + b2;
                *(__nv_bfloat16*)(smem + OFF_BHI + off) = hi;
                *(__nv_bfloat16*)(smem + OFF_BLO + off) = lo;
            }
        }
        __syncthreads();

        // ---- compute: 4 k16-steps, 3 split-terms ----
        #pragma unroll
        for (int ks = 0; ks < 4; ks++) {
            uint32_t ahi[2][4], alo[2][4], bf[7][2];
            #pragma unroll
            for (int t = 0; t < 2; t++) {
                uint32_t aoff = SWADDR(arow0 + t*16, ks*2 + ac16);
                ldm_x4(ahi[t], sbase + OFF_AHI + aoff);
                ldm_x4(alo[t], sbase + OFF_ALO + aoff);
            }
            // pass 1+2: (Ahi + Alo) x Bhi
            #pragma unroll
            for (int nt = 0; nt < 7; nt++) {
                uint32_t boff = SWADDR(warp_n + nt*8 + brow_l, ks*2 + bc16);
                ldm_x2(bf[nt], sbase + OFF_BHI + boff);
            }
            #pragma unroll
            for (int nt = 0; nt < 7; nt++)
                #pragma unroll
                for (int t = 0; t < 2; t++)
                    mma16816(acc[t][nt], ahi[t], bf[nt]);
            #pragma unroll
            for (int nt = 0; nt < 7; nt++)
                #pragma unroll
                for (int t = 0; t < 2; t++)
                    mma16816(acc[t][nt], alo[t], bf[nt]);
            // pass 3: Ahi x Blo
            #pragma unroll
            for (int nt = 0; nt < 7; nt++) {
                uint32_t boff = SWADDR(warp_n + nt*8 + brow_l, ks*2 + bc16);
                ldm_x2(bf[nt], sbase + OFF_BLO + boff);
            }
            #pragma unroll
            for (int nt = 0; nt < 7; nt++)
                #pragma unroll
                for (int t = 0; t < 2; t++)
                    mma16816(acc[t][nt], ahi[t], bf[nt]);
        }
        __syncthreads();
    }

    // ---- epilogue: D frag -> gmem with bias ----
    int r4 = lane >> 2;
    int c2 = (lane & 3) * 2;
    #pragma unroll
    for (int t = 0; t < 2; t++) {
        int or0 = m0 + warp_m + t*16 + r4;
        float bi0 = bias[or0];
        float bi1 = bias[or0 + 8];
        float* op0 = out + ((size_t)b * COUT + or0    ) * HW + n0 + warp_n + c2;
        float* op1 = out + ((size_t)b * COUT + or0 + 8) * HW + n0 + warp_n + c2;
        #pragma unroll
        for (int nt = 0; nt < 7; nt++) {
            float2 v0 = make_float2(acc[t][nt][0] + bi0, acc[t][nt][1] + bi0);
            float2 v1 = make_float2(acc[t][nt][2] + bi1, acc[t][nt][3] + bi1);
            *(float2*)(op0 + nt*8) = v0;
            *(float2*)(op1 + nt*8) = v1;
        }
    }
}

// ---------------- launch ----------------
extern "C" void kernel_launch(void* const* d_in, const int* in_sizes, int n_in,
                              void* d_out, int out_size) {
    const float* x    = (const float*)d_in[0];
    const float* bk   = (const float*)d_in[1];
    const float* bias = (const float*)d_in[2];
    const float* fsw  = (const float*)d_in[3];
    const float* fsb  = (const float*)d_in[4];
    const float* fiw  = (const float*)d_in[5];
    const float* fib  = (const float*)d_in[6];
    const float* fow  = (const float*)d_in[7];
    const float* fob  = (const float*)d_in[8];
    const float* fkw  = (const float*)d_in[9];
    const float* fkb  = (const float*)d_in[10];
    float* out = (float*)d_out;

    k_context<<<BB*CIN, 256>>>(x);

    int total_warps = BB * (KK + CIN + COUT);
    k_attn<<<(total_warps*32 + 255)/256, 256>>>(fsw, fsb, fiw, fib, fow, fob);

    k_dyn<<<(COUT*KDIM)/256, 256>>>(bk, fkw, fkb);

    cudaFuncSetAttribute(k_conv_mma, cudaFuncAttributeMaxDynamicSharedMemorySize,
                         SMEM_BYTES);
    dim3 grid(HW/BN, COUT/BM, BB);   // (28, 2, 16)
    k_conv_mma<<<grid, 256, SMEM_BYTES>>>(x, bias, out);
}

// round 4
// speedup vs baseline: 2.1779x; 1.0295x over previous
#include <cuda_runtime.h>
#include <cuda_bf16.h>
#include <cstdint>
#include <math.h>

#define BB   16
#define CIN  128
#define COUT 256
#define KK   9
#define HH   56
#define WW   56
#define HW   3136
#define KDIM (CIN*KK)   // 1152
#define HP   58         // padded H/W

// GEMM tiling (mma.sync bf16 path)
#define BM 128
#define BN 112          // 3136 = 28 * 112 ; covers exactly 2 image rows
#define BK 64           // bf16 K per mainloop chunk
#define NCHUNK (KDIM/BK) // 18

// ---------------- device scratch (no allocations allowed) ----------------
__device__ float g_ctx[BB*CIN];
__device__ float g_attn_sp[BB*KK];
__device__ float g_attn_in[BB*CIN];
__device__ float g_attn_out[BB*COUT];
__device__ __align__(16) __nv_bfloat16 g_dynA_hi[(size_t)BB*COUT*KDIM]; // 9.4MB
__device__ __align__(16) __nv_bfloat16 g_dynA_lo[(size_t)BB*COUT*KDIM]; // 9.4MB
__device__ __align__(16) uint32_t g_xpad[(size_t)BB*CIN*HP*HP];         // 27.5MB (hi|lo<<16)

// ======================= helpers =====================
__device__ __forceinline__ uint32_t smem_u32(const void* p) {
    uint32_t a;
    asm("{ .reg .u64 t; cvta.to.shared.u64 t, %1; cvt.u32.u64 %0, t; }"
        : "=r"(a) : "l"(p));
    return a;
}
__device__ __forceinline__ void ldm_x4(uint32_t* r, uint32_t addr) {
    asm volatile("ldmatrix.sync.aligned.m8n8.x4.shared.b16 {%0,%1,%2,%3}, [%4];"
        : "=r"(r[0]), "=r"(r[1]), "=r"(r[2]), "=r"(r[3]) : "r"(addr));
}
__device__ __forceinline__ void ldm_x2(uint32_t* r, uint32_t addr) {
    asm volatile("ldmatrix.sync.aligned.m8n8.x2.shared.b16 {%0,%1}, [%2];"
        : "=r"(r[0]), "=r"(r[1]) : "r"(addr));
}
__device__ __forceinline__ void mma16816(float* d, const uint32_t* a, const uint32_t* b) {
    asm volatile("mma.sync.aligned.m16n8k16.row.col.f32.bf16.bf16.f32 "
        "{%0,%1,%2,%3}, {%4,%5,%6,%7}, {%8,%9}, {%0,%1,%2,%3};"
        : "+f"(d[0]), "+f"(d[1]), "+f"(d[2]), "+f"(d[3])
        : "r"(a[0]), "r"(a[1]), "r"(a[2]), "r"(a[3]), "r"(b[0]), "r"(b[1]));
}
__device__ __forceinline__ void cp16(uint32_t dst, const void* src) {
    asm volatile("cp.async.cg.shared.global [%0], [%1], 16;"
        :: "r"(dst), "l"(src));
}
#define CP_COMMIT() asm volatile("cp.async.commit_group;" ::: "memory")
#define CP_WAIT0()  asm volatile("cp.async.wait_group 0;" ::: "memory")

// 128B-row smem tile, XOR swizzle on 16B columns (conflict-free ldmatrix)
#define SWADDR(row, c16) ((uint32_t)((row) * 128 + (((c16) ^ ((row) & 7)) << 4)))

// ---------------- 1) context = mean over H,W ----------------
__global__ void k_context(const float* __restrict__ x) {
    int row = blockIdx.x;
    const float* p = x + (size_t)row * HW;
    float s = 0.f;
    for (int i = threadIdx.x; i < HW; i += 256) s += p[i];
    __shared__ float sm[256];
    sm[threadIdx.x] = s; __syncthreads();
    #pragma unroll
    for (int off = 128; off > 0; off >>= 1) {
        if (threadIdx.x < off) sm[threadIdx.x] += sm[threadIdx.x + off];
        __syncthreads();
    }
    if (threadIdx.x == 0) g_ctx[row] = sm[0] * (1.0f / HW);
}

// ---------------- 1b) pad + bf16-split x into packed u32 ----------------
__global__ void k_pad(const float* __restrict__ x) {
    int idx = blockIdx.x * 256 + threadIdx.x;
    const int total = BB*CIN*HP*HP;
    if (idx >= total) return;
    int wp = idx % HP;
    int t  = idx / HP;
    int hp = t % HP;
    int pc = t / HP;                 // b*CIN + ci
    float v = 0.f;
    if (hp >= 1 && hp <= HH && wp >= 1 && wp <= WW)
        v = x[(size_t)pc * HW + (hp - 1) * WW + (wp - 1)];
    __nv_bfloat16 hi = __float2bfloat16(v);
    __nv_bfloat16 lo = __float2bfloat16(v - __bfloat162float(hi));
    __nv_bfloat16_raw hr = hi, lr = lo;
    g_xpad[idx] = (uint32_t)hr.x | ((uint32_t)lr.x << 16);
}

// ---------------- 2) small attention heads ----------------
__global__ void k_attn(const float* __restrict__ fsw, const float* __restrict__ fsb,
                       const float* __restrict__ fiw, const float* __restrict__ fib,
                       const float* __restrict__ fow, const float* __restrict__ fob) {
    int gw   = (blockIdx.x * blockDim.x + threadIdx.x) >> 5;
    int lane = threadIdx.x & 31;
    const int NS = BB*KK, NI = BB*CIN, NO = BB*COUT;
    if (gw >= NS + NI + NO) return;
    int b; const float* wrow; float bias; float* dst;
    if (gw < NS) {
        b = gw / KK; int r = gw % KK;
        wrow = fsw + r*CIN; bias = fsb[r]; dst = &g_attn_sp[gw];
    } else if (gw < NS + NI) {
        int g = gw - NS; b = g / CIN; int r = g % CIN;
        wrow = fiw + r*CIN; bias = fib[r]; dst = &g_attn_in[g];
    } else {
        int g = gw - NS - NI; b = g / COUT; int r = g % COUT;
        wrow = fow + r*CIN; bias = fob[r]; dst = &g_attn_out[g];
    }
    const float* ctx = g_ctx + b*CIN;
    float s = 0.f;
    #pragma unroll
    for (int j = lane; j < CIN; j += 32) s += ctx[j] * wrow[j];
    #pragma unroll
    for (int o = 16; o > 0; o >>= 1) s += __shfl_down_sync(0xffffffffu, s, o);
    if (lane == 0) *dst = 1.f / (1.f + expf(-(s + bias)));
}

// ------- 3) fused big-GEMM + sigmoid + 5-way multiply -> bf16 hi/lo -------
__global__ __launch_bounds__(256) void k_dyn(const float* __restrict__ base_kernel,
                                             const float* __restrict__ fkw,
                                             const float* __restrict__ fkb) {
    __shared__ __align__(16) float ctx_s[BB*CIN];
    for (int i = threadIdx.x; i < BB*CIN; i += 256) ctx_s[i] = g_ctx[i];
    __syncthreads();

    int r = blockIdx.x * 256 + threadIdx.x;          // 0..294911
    const float4* wr = (const float4*)(fkw + (size_t)r * CIN);

    float acc[BB];
    #pragma unroll
    for (int b = 0; b < BB; b++) acc[b] = 0.f;

    #pragma unroll 4
    for (int j = 0; j < CIN/4; j++) {
        float4 w4 = wr[j];
        #pragma unroll
        for (int b = 0; b < BB; b++) {
            float4 c4 = *(const float4*)(ctx_s + b*CIN + j*4);
            acc[b] += w4.x*c4.x + w4.y*c4.y + w4.z*c4.z + w4.w*c4.w;
        }
    }

    int o   = r / KDIM;
    int rem = r - o*KDIM;
    int i   = rem / KK;
    int kk  = rem - i*KK;
    float bk = base_kernel[r];
    float fb = fkb[r];
    #pragma unroll
    for (int b = 0; b < BB; b++) {
        float sg = 1.f / (1.f + expf(-(acc[b] + fb)));
        float v  = bk * g_attn_out[b*COUT + o] * g_attn_in[b*CIN + i]
                      * g_attn_sp[b*KK + kk] * sg;
        __nv_bfloat16 hi = __float2bfloat16(v);
        __nv_bfloat16 lo = __float2bfloat16(v - __bfloat162float(hi));
        size_t idx = (size_t)b * COUT * KDIM + r;
        g_dynA_hi[idx] = hi;
        g_dynA_lo[idx] = lo;
    }
}

// -------- 4) tensor-core conv via mma.sync bf16, double-buffered ----------
// Per stage: Ahi 16KB | Alo 16KB | Bhi 14KB | Blo 14KB = 60KB; 2 stages.
#define OFF_AHI  0
#define OFF_ALO  16384
#define OFF_BHI  32768
#define OFF_BLO  47104
#define STG      61440
#define SMEM_BYTES (2*STG)   // 122880

__global__ __launch_bounds__(256, 1) void k_conv_mma(const float* __restrict__ bias,
                                                     float* __restrict__ out) {
    extern __shared__ char smem[];
    uint32_t sbase = smem_u32(smem);
    int tid  = threadIdx.x;
    int wid  = tid >> 5;
    int lane = tid & 31;

    int b  = blockIdx.z;
    int m0 = blockIdx.y * BM;
    int n0 = blockIdx.x * BN;

    const __nv_bfloat16* Ahi = g_dynA_hi + (size_t)(b*COUT + m0) * KDIM;
    const __nv_bfloat16* Alo = g_dynA_lo + (size_t)(b*COUT + m0) * KDIM;
    const uint32_t* Xp = g_xpad + (size_t)b * CIN * HP * HP;

    // warp tile: 32(m) x 56(n)
    int warp_m = (wid & 3) * 32;
    int warp_n = (wid >> 2) * 56;

    // per-lane ldmatrix addressing
    int amat  = lane >> 3;
    int arow0 = warp_m + (amat & 1) * 8 + (lane & 7);
    int ac16  = amat >> 1;
    int brow_l = (lane & 7);
    int bc16   = (lane >> 3) & 1;

    // B gather mapping: kc = tid>>2 (0..63), q = tid&3
    int kc = tid >> 2;
    int q  = tid & 3;
    int h_local = q >> 1;
    int w0 = (q & 1) * 28;
    int nbase = q * 28;
    int hbase = blockIdx.x * 2;
    int c16b = kc >> 3;
    int b2   = (kc & 7) * 2;

    float acc[2][7][4];
    #pragma unroll
    for (int t = 0; t < 2; t++)
        #pragma unroll
        for (int nt = 0; nt < 7; nt++)
            #pragma unroll
            for (int i = 0; i < 4; i++) acc[t][nt][i] = 0.f;

    // ---- helpers as lambdas ----
    auto loadA = [&](int kt, uint32_t stg_off) {
        int k0 = kt * BK;
        #pragma unroll
        for (int c = 0; c < 4; c++) {
            int idx = c * 256 + tid;
            int row = idx >> 3;
            int c16 = idx & 7;
            size_t src = (size_t)row * KDIM + k0 + c16 * 8;
            uint32_t off = SWADDR(row, c16);
            cp16(sbase + stg_off + OFF_AHI + off, Ahi + src);
            cp16(sbase + stg_off + OFF_ALO + off, Alo + src);
        }
    };
    auto gatherLd = [&](int kt, uint32_t* pf) {
        int k  = kt * BK + kc;
        int ci = k / 9;
        int r9 = k - ci * 9;
        int kh = r9 / 3;
        int kw = r9 - kh * 3;
        const uint32_t* src = Xp + (size_t)(ci * HP + hbase + h_local + kh) * HP
                                 + (w0 + kw);
        #pragma unroll
        for (int j = 0; j < 28; j++) pf[j] = src[j];
    };
    auto gatherSt = [&](const uint32_t* pf, uint32_t stg_off) {
        #pragma unroll
        for (int j = 0; j < 28; j++) {
            uint32_t off = SWADDR(nbase + j, c16b) + b2;
            *(uint16_t*)(smem + stg_off + OFF_BHI + off) = (uint16_t)pf[j];
            *(uint16_t*)(smem + stg_off + OFF_BLO + off) = (uint16_t)(pf[j] >> 16);
        }
    };

    // ---- prologue: stage 0 = chunk 0 ----
    {
        uint32_t pf[28];
        loadA(0, 0);
        CP_COMMIT();
        gatherLd(0, pf);
        gatherSt(pf, 0);
    }

    for (int kt = 0; kt < NCHUNK; kt++) {
        uint32_t s_off  = (kt & 1) ? STG : 0;
        uint32_t n_off  = (kt & 1) ? 0 : STG;
        CP_WAIT0();
        __syncthreads();

        bool hn = (kt + 1) < NCHUNK;
        uint32_t pf[28];
        if (hn) {
            loadA(kt + 1, n_off);
            CP_COMMIT();
            gatherLd(kt + 1, pf);
        }

        // ---- compute: 4 k16-steps, 3 split-terms ----
        #pragma unroll
        for (int ks = 0; ks < 4; ks++) {
            uint32_t ahi[2][4], alo[2][4], bf[7][2];
            #pragma unroll
            for (int t = 0; t < 2; t++) {
                uint32_t aoff = SWADDR(arow0 + t*16, ks*2 + ac16);
                ldm_x4(ahi[t], sbase + s_off + OFF_AHI + aoff);
                ldm_x4(alo[t], sbase + s_off + OFF_ALO + aoff);
            }
            #pragma unroll
            for (int nt = 0; nt < 7; nt++) {
                uint32_t boff = SWADDR(warp_n + nt*8 + brow_l, ks*2 + bc16);
                ldm_x2(bf[nt], sbase + s_off + OFF_BHI + boff);
            }
            #pragma unroll
            for (int nt = 0; nt < 7; nt++)
                #pragma unroll
                for (int t = 0; t < 2; t++)
                    mma16816(acc[t][nt], ahi[t], bf[nt]);
            #pragma unroll
            for (int nt = 0; nt < 7; nt++)
                #pragma unroll
                for (int t = 0; t < 2; t++)
                    mma16816(acc[t][nt], alo[t], bf[nt]);
            #pragma unroll
            for (int nt = 0; nt < 7; nt++) {
                uint32_t boff = SWADDR(warp_n + nt*8 + brow_l, ks*2 + bc16);
                ldm_x2(bf[nt], sbase + s_off + OFF_BLO + boff);
            }
            #pragma unroll
            for (int nt = 0; nt < 7; nt++)
                #pragma unroll
                for (int t = 0; t < 2; t++)
                    mma16816(acc[t][nt], ahi[t], bf[nt]);
        }

        if (hn) gatherSt(pf, n_off);
    }

    // ---- epilogue: D frag -> gmem with bias ----
    int r4 = lane >> 2;
    int c2 = (lane & 3) * 2;
    #pragma unroll
    for (int t = 0; t < 2; t++) {
        int or0 = m0 + warp_m + t*16 + r4;
        float bi0 = bias[or0];
        float bi1 = bias[or0 + 8];
        float* op0 = out + ((size_t)b * COUT + or0    ) * HW + n0 + warp_n + c2;
        float* op1 = out + ((size_t)b * COUT + or0 + 8) * HW + n0 + warp_n + c2;
        #pragma unroll
        for (int nt = 0; nt < 7; nt++) {
            float2 v0 = make_float2(acc[t][nt][0] + bi0, acc[t][nt][1] + bi0);
            float2 v1 = make_float2(acc[t][nt][2] + bi1, acc[t][nt][3] + bi1);
            *(float2*)(op0 + nt*8) = v0;
            *(float2*)(op1 + nt*8) = v1;
        }
    }
}

// ---------------- launch ----------------
extern "C" void kernel_launch(void* const* d_in, const int* in_sizes, int n_in,
                              void* d_out, int out_size) {
    const float* x    = (const float*)d_in[0];
    const float* bk   = (const float*)d_in[1];
    const float* bias = (const float*)d_in[2];
    const float* fsw  = (const float*)d_in[3];
    const float* fsb  = (const float*)d_in[4];
    const float* fiw  = (const float*)d_in[5];
    const float* fib  = (const float*)d_in[6];
    const float* fow  = (const float*)d_in[7];
    const float* fob  = (const float*)d_in[8];
    const float* fkw  = (const float*)d_in[9];
    const float* fkb  = (const float*)d_in[10];
    float* out = (float*)d_out;

    k_context<<<BB*CIN, 256>>>(x);
    k_pad<<<(BB*CIN*HP*HP + 255)/256, 256>>>(x);

    int total_warps = BB * (KK + CIN + COUT);
    k_attn<<<(total_warps*32 + 255)/256, 256>>>(fsw, fsb, fiw, fib, fow, fob);

    k_dyn<<<(COUT*KDIM)/256, 256>>>(bk, fkw, fkb);

    cudaFuncSetAttribute(k_conv_mma, cudaFuncAttributeMaxDynamicSharedMemorySize,
                         SMEM_BYTES);
    dim3 grid(HW/BN, COUT/BM, BB);   // (28, 2, 16)
    k_conv_mma<<<grid, 256, SMEM_BYTES>>>(bias, out);
}